// round 12
// baseline (speedup 1.0000x reference)
#include <cuda_runtime.h>
#include <cstdint>

#define NBLK 444            // 3 blocks/SM * 148 SMs -> one wave (66.6KB smem/block)
#define NTHR 256
#define STAGES 4
#define TILE_F4 512         // 512 float4 = 8KB per array per stage (16KB/stage)
#define TILE_BYTES (TILE_F4 * 16)

// dynamic smem layout (bytes)
#define SMEM_BX   0
#define SMEM_BD   (STAGES * TILE_BYTES)              // 32KB
#define SMEM_RED  (2 * STAGES * TILE_BYTES)          // 64KB
#define SMEM_MBAR (SMEM_RED + NTHR * 4)              // 65KB
#define SMEM_TOTAL (SMEM_MBAR + STAGES * 8 + 16)

__device__ float        g_partials[NBLK];
__device__ unsigned int g_ticket;   // zero-init; reset by last block each launch

__device__ __forceinline__ unsigned smem_u32(const void* p) {
    return (unsigned)__cvta_generic_to_shared(p);
}

__device__ __forceinline__ void mbar_init(unsigned addr, unsigned count) {
    asm volatile("mbarrier.init.shared.b64 [%0], %1;" :: "r"(addr), "r"(count) : "memory");
}

__device__ __forceinline__ void mbar_wait(unsigned addr, unsigned parity) {
    asm volatile(
        "{\n\t"
        ".reg .pred P;\n\t"
        "WAIT_%=:\n\t"
        "mbarrier.try_wait.parity.acquire.cta.shared::cta.b64 P, [%0], %1, 0x989680;\n\t"
        "@P bra.uni DONE_%=;\n\t"
        "bra.uni WAIT_%=;\n\t"
        "DONE_%=:\n\t"
        "}"
        :: "r"(addr), "r"(parity) : "memory");
}

// Issue one stage: expect 16KB, two 8KB bulk copies into slot.
__device__ __forceinline__ void issue_tile(unsigned mbar, unsigned dst_x, unsigned dst_d,
                                           const float4* src_x, const float4* src_d) {
    asm volatile("fence.proxy.async.shared::cta;" ::: "memory");
    asm volatile("mbarrier.arrive.expect_tx.shared.b64 _, [%0], %1;"
                 :: "r"(mbar), "r"((unsigned)(2 * TILE_BYTES)) : "memory");
    asm volatile("cp.async.bulk.shared::cluster.global.mbarrier::complete_tx::bytes [%0], [%1], %2, [%3];"
                 :: "r"(dst_x), "l"(src_x), "r"((unsigned)TILE_BYTES), "r"(mbar) : "memory");
    asm volatile("cp.async.bulk.shared::cluster.global.mbarrier::complete_tx::bytes [%0], [%1], %2, [%3];"
                 :: "r"(dst_d), "l"(src_d), "r"((unsigned)TILE_BYTES), "r"(mbar) : "memory");
}

__global__ __launch_bounds__(NTHR, 3) void le_fused(
    const float* __restrict__ x,
    const float* __restrict__ decoded,
    const float* __restrict__ encoded,
    const float* __restrict__ latent,
    const float* __restrict__ rsrA,
    float* __restrict__ out,
    int B, int D, int E, int I)
{
    extern __shared__ char smem[];
    float4* __restrict__ bx  = (float4*)(smem + SMEM_BX);
    float4* __restrict__ bd  = (float4*)(smem + SMEM_BD);
    float*  __restrict__ red = (float*)(smem + SMEM_RED);
    const unsigned mb0 = smem_u32(smem + SMEM_MBAR);

    const int tid = threadIdx.x;
    const int bid = blockIdx.x;

    if (tid == 0) {
        #pragma unroll
        for (int s = 0; s < STAGES; s++) mbar_init(mb0 + 8u * s, 1u);
    }
    __syncthreads();

    const int n4 = (B * D) >> 2;          // float4 count per array
    const int nt = n4 / TILE_F4;          // 8KB tiles per array
    const float4* __restrict__ x4 = (const float4*)x;
    const float4* __restrict__ d4 = (const float4*)decoded;

    const int ntiles = (bid < nt) ? ((nt - bid + NBLK - 1) / NBLK) : 0;

    // ---- Prologue: queue up to STAGES tiles via TMA bulk (64KB/block) ----
    if (tid == 0) {
        const int npro = ntiles < STAGES ? ntiles : STAGES;
        for (int lt = 0; lt < npro; lt++) {
            const int g = bid + lt * NBLK;
            issue_tile(mb0 + 8u * lt,
                       smem_u32(&bx[lt * TILE_F4]), smem_u32(&bd[lt * TILE_F4]),
                       x4 + (size_t)g * TILE_F4, d4 + (size_t)g * TILE_F4);
        }
    }

    // ======== Phase 2 (overlaps TMA prologue stream): ========
    //   thread owns column e = tid & 127; rsrA row in registers;
    //   latent rows are warp-uniform broadcasts; encoded coalesced.
    float acc2 = 0.0f;
    {
        const int e    = tid & 127;          // E == 128
        const int half = tid >> 7;           // 0/1 split of this block's rows
        // load my rsrA row (20 floats = 5 float4; rows are 80B, 16B-aligned)
        const float4* __restrict__ Ar = (const float4*)(rsrA + e * 20);
        float4 A0 = __ldg(Ar + 0), A1 = __ldg(Ar + 1), A2 = __ldg(Ar + 2),
               A3 = __ldg(Ar + 3), A4 = __ldg(Ar + 4);

        for (int b = bid + half * NBLK; b < B; b += 2 * NBLK) {
            const float4* __restrict__ L = (const float4*)(latent + b * 20);
            float4 l0 = __ldg(L + 0), l1 = __ldg(L + 1), l2 = __ldg(L + 2),
                   l3 = __ldg(L + 3), l4 = __ldg(L + 4);
            float z = 0.0f;
            z = fmaf(A0.x, l0.x, z); z = fmaf(A0.y, l0.y, z);
            z = fmaf(A0.z, l0.z, z); z = fmaf(A0.w, l0.w, z);
            z = fmaf(A1.x, l1.x, z); z = fmaf(A1.y, l1.y, z);
            z = fmaf(A1.z, l1.z, z); z = fmaf(A1.w, l1.w, z);
            z = fmaf(A2.x, l2.x, z); z = fmaf(A2.y, l2.y, z);
            z = fmaf(A2.z, l2.z, z); z = fmaf(A2.w, l2.w, z);
            z = fmaf(A3.x, l3.x, z); z = fmaf(A3.y, l3.y, z);
            z = fmaf(A3.z, l3.z, z); z = fmaf(A3.w, l3.w, z);
            z = fmaf(A4.x, l4.x, z); z = fmaf(A4.y, l4.y, z);
            z = fmaf(A4.z, l4.z, z); z = fmaf(A4.w, l4.w, z);
            const float d = encoded[b * 128 + e] - z;
            acc2 = fmaf(d, d, acc2);
        }
    }

    // ======== Phase 1: consume TMA ring, sum (x - decoded)^2 ========
    float acc1 = 0.0f;
    for (int lt = 0; lt < ntiles; lt++) {
        const int slot = lt & (STAGES - 1);
        const unsigned parity = ((unsigned)lt / STAGES) & 1u;
        mbar_wait(mb0 + 8u * slot, parity);

        // 2 float4 per array per thread
        const int o = slot * TILE_F4 + tid;
        float4 a0 = bx[o];          float4 c0 = bd[o];
        float4 a1 = bx[o + NTHR];   float4 c1 = bd[o + NTHR];

        __syncthreads();   // slot drained -> safe to refill
        if (tid == 0 && lt + STAGES < ntiles) {
            const int g = bid + (lt + STAGES) * NBLK;
            issue_tile(mb0 + 8u * slot,
                       smem_u32(&bx[slot * TILE_F4]), smem_u32(&bd[slot * TILE_F4]),
                       x4 + (size_t)g * TILE_F4, d4 + (size_t)g * TILE_F4);
        }

        float t;
        t = a0.x - c0.x; acc1 = fmaf(t, t, acc1);
        t = a0.y - c0.y; acc1 = fmaf(t, t, acc1);
        t = a0.z - c0.z; acc1 = fmaf(t, t, acc1);
        t = a0.w - c0.w; acc1 = fmaf(t, t, acc1);
        t = a1.x - c1.x; acc1 = fmaf(t, t, acc1);
        t = a1.y - c1.y; acc1 = fmaf(t, t, acc1);
        t = a1.z - c1.z; acc1 = fmaf(t, t, acc1);
        t = a1.w - c1.w; acc1 = fmaf(t, t, acc1);
    }
    // remainder (none for canonical shape, kept for safety)
    for (int i = nt * TILE_F4 + bid * NTHR + tid; i < n4; i += NBLK * NTHR) {
        float4 a = x4[i], c = d4[i];
        float t;
        t = a.x - c.x; acc1 = fmaf(t, t, acc1);
        t = a.y - c.y; acc1 = fmaf(t, t, acc1);
        t = a.z - c.z; acc1 = fmaf(t, t, acc1);
        t = a.w - c.w; acc1 = fmaf(t, t, acc1);
    }

    // ======== Gram term (block 0, rsrA via L1): w*Sg, w = 0.1*B/(I*I) ========
    float extra = 0.0f;
    if (bid == 0) {
        float sg = 0.0f;
        for (int t = tid; t < I * I; t += NTHR) {
            const int gi = t / 20, gj = t % 20;
            float acc = 0.0f;
            #pragma unroll 8
            for (int e = 0; e < 128; e++)
                acc = fmaf(__ldg(rsrA + e * 20 + gi), __ldg(rsrA + e * 20 + gj), acc);
            if (gi == gj) acc -= 1.0f;
            sg = fmaf(acc, acc, sg);
        }
        extra = (0.1f * (float)B / (float)(I * I)) * sg;
    }

    // ======== Deterministic block reduction ========
    red[tid] = acc1 + 1.1f * acc2 + extra;
    __syncthreads();
    for (int s = NTHR / 2; s > 0; s >>= 1) {
        if (tid < s) red[tid] += red[tid + s];
        __syncthreads();
    }

    // ======== Last-block final reduction ========
    __shared__ bool is_last;
    if (tid == 0) {
        g_partials[bid] = red[0];
        __threadfence();
        unsigned int t = atomicAdd(&g_ticket, 1u);
        is_last = (t == (unsigned int)(gridDim.x - 1));
    }
    __syncthreads();

    if (is_last) {
        __threadfence();
        float p = 0.0f;
        for (int k = tid; k < NBLK; k += NTHR)
            p += g_partials[k];
        red[tid] = p;
        __syncthreads();
        for (int s = NTHR / 2; s > 0; s >>= 1) {
            if (tid < s) red[tid] += red[tid + s];
            __syncthreads();
        }
        if (tid == 0) {
            out[0] = red[0] / (float)B;
            g_ticket = 0;
        }
    }
}

extern "C" void kernel_launch(void* const* d_in, const int* in_sizes, int n_in,
                              void* d_out, int out_size)
{
    const float* x       = (const float*)d_in[0];
    const float* encoded = (const float*)d_in[1];
    const float* latent  = (const float*)d_in[2];
    const float* decoded = (const float*)d_in[3];
    const float* rsrA    = (const float*)d_in[4];

    const int I = 20;                  // INTRINSIC
    const int B = in_sizes[2] / I;     // latent [B, I]
    const int E = in_sizes[1] / B;     // encoded [B, E]
    const int D = in_sizes[0] / B;     // x [B, D]

    // raise dynamic smem cap (idempotent; host-side attribute, not an allocation)
    cudaFuncSetAttribute(le_fused, cudaFuncAttributeMaxDynamicSharedMemorySize,
                         SMEM_TOTAL);

    le_fused<<<NBLK, NTHR, SMEM_TOTAL>>>(x, decoded, encoded, latent, rsrA,
                                         (float*)d_out, B, D, E, I);
}

// round 13
// speedup vs baseline: 1.7008x; 1.7008x over previous
#include <cuda_runtime.h>
#include <cstdint>

#define NBLK 592          // 4 blocks/SM * 148 SMs -> one wave
#define NB_TMA 326        // blocks on the TMA path (~55% of stream)
#define NB_LDG (NBLK - NB_TMA)
#define NTHR 256
#define STAGES 4
#define TILE_F4 256       // 4KB per array per stage (8KB/stage)

__device__ float        g_partials[NBLK];
__device__ unsigned int g_ticket;   // zero-init; reset by last block each launch

__device__ __forceinline__ unsigned smem_u32(const void* p) {
    return (unsigned)__cvta_generic_to_shared(p);
}

__device__ __forceinline__ void mbar_init(unsigned addr, unsigned count) {
    asm volatile("mbarrier.init.shared.b64 [%0], %1;" :: "r"(addr), "r"(count) : "memory");
}

__device__ __forceinline__ void mbar_wait(unsigned addr, unsigned parity) {
    asm volatile(
        "{\n\t"
        ".reg .pred P;\n\t"
        "WAIT_%=:\n\t"
        "mbarrier.try_wait.parity.acquire.cta.shared::cta.b64 P, [%0], %1, 0x989680;\n\t"
        "@P bra.uni DONE_%=;\n\t"
        "bra.uni WAIT_%=;\n\t"
        "DONE_%=:\n\t"
        "}"
        :: "r"(addr), "r"(parity) : "memory");
}

// Issue one stage: expect 8KB, two 4KB bulk copies into slot.
__device__ __forceinline__ void issue_tile(unsigned mbar, unsigned dst_x, unsigned dst_d,
                                           const float4* src_x, const float4* src_d) {
    asm volatile("fence.proxy.async.shared::cta;" ::: "memory");
    asm volatile("mbarrier.arrive.expect_tx.shared.b64 _, [%0], %1;"
                 :: "r"(mbar), "r"(8192u) : "memory");
    asm volatile("cp.async.bulk.shared::cluster.global.mbarrier::complete_tx::bytes [%0], [%1], %2, [%3];"
                 :: "r"(dst_x), "l"(src_x), "r"(4096u), "r"(mbar) : "memory");
    asm volatile("cp.async.bulk.shared::cluster.global.mbarrier::complete_tx::bytes [%0], [%1], %2, [%3];"
                 :: "r"(dst_d), "l"(src_d), "r"(4096u), "r"(mbar) : "memory");
}

__global__ __launch_bounds__(NTHR, 4) void le_fused(
    const float* __restrict__ x,
    const float* __restrict__ decoded,
    const float* __restrict__ encoded,
    const float* __restrict__ latent,
    const float* __restrict__ rsrA,
    float* __restrict__ out,
    int B, int D, int E, int I)
{
    __shared__ float4 bx[STAGES][TILE_F4];     // 16KB (TMA blocks only)
    __shared__ float4 bd[STAGES][TILE_F4];     // 16KB
    __shared__ float  sA[128 * 21];            // 10.5KB rsrA cache (phase 2)
    __shared__ float  red[NTHR];               // 1KB
    __shared__ alignas(8) unsigned long long mbar_store[STAGES];

    const int tid = threadIdx.x;
    const int bid = blockIdx.x;
    const unsigned mb0 = smem_u32(&mbar_store[0]);

    // rsrA cache (stride 21 -> conflict-free); needed by all blocks for phase 2
    for (int i = tid; i < E * I; i += NTHR) {
        int e = i / 20, k = i % 20;
        sA[e * 21 + k] = rsrA[i];
    }
    if (tid == 0) {
        #pragma unroll
        for (int s = 0; s < STAGES; s++) mbar_init(mb0 + 8u * s, 1u);
    }
    __syncthreads();

    const int n4 = (B * D) >> 2;          // float4 count per array
    const int nt = n4 / TILE_F4;          // total 4KB tiles per array
    const int nt_tma = (int)(((long long)nt * 11) / 20);   // ~55% via TMA
    const float4* __restrict__ x4 = (const float4*)x;
    const float4* __restrict__ d4 = (const float4*)decoded;

    const bool is_tma = (bid < NB_TMA);

    // TMA blocks: tiles g = bid, bid+NB_TMA, ... < nt_tma
    const int ntiles = (is_tma && bid < nt_tma)
                     ? ((nt_tma - bid + NB_TMA - 1) / NB_TMA) : 0;

    // ---- Prologue (TMA blocks): queue up to STAGES tiles ----
    if (is_tma && tid == 0) {
        const int npro = ntiles < STAGES ? ntiles : STAGES;
        for (int lt = 0; lt < npro; lt++) {
            const int g = bid + lt * NB_TMA;
            issue_tile(mb0 + 8u * lt,
                       smem_u32(&bx[lt][0]), smem_u32(&bd[lt][0]),
                       x4 + (size_t)g * TILE_F4, d4 + (size_t)g * TILE_F4);
        }
    }

    // ======== Phase 2 (all blocks; overlaps TMA prologue): ========
    //          sum (encoded - latent@A^T)^2, 4 independent slots
    float acc2 = 0.0f;
    {
        const int gtid   = bid * NTHR + tid;
        const int stride = NBLK * NTHR;
        const int n2 = B * E;
        int j = gtid;
        const int s = stride;
        for (; j + 3 * s < n2; j += 4 * s) {
            float z0 = 0.f, z1 = 0.f, z2 = 0.f, z3 = 0.f;
            const int j0 = j, j1 = j + s, j2 = j + 2*s, j3 = j + 3*s;
            const float4* __restrict__ L0 = (const float4*)(latent + (j0 >> 7) * 20);
            const float4* __restrict__ L1 = (const float4*)(latent + (j1 >> 7) * 20);
            const float4* __restrict__ L2 = (const float4*)(latent + (j2 >> 7) * 20);
            const float4* __restrict__ L3 = (const float4*)(latent + (j3 >> 7) * 20);
            const float* __restrict__ A0 = sA + (j0 & 127) * 21;
            const float* __restrict__ A1 = sA + (j1 & 127) * 21;
            const float* __restrict__ A2 = sA + (j2 & 127) * 21;
            const float* __restrict__ A3 = sA + (j3 & 127) * 21;
            float e0 = encoded[j0], e1 = encoded[j1],
                  e2 = encoded[j2], e3 = encoded[j3];
            #pragma unroll
            for (int q = 0; q < 5; q++) {
                float4 l0 = L0[q], l1 = L1[q], l2 = L2[q], l3 = L3[q];
                z0 = fmaf(l0.x, A0[4*q+0], z0); z0 = fmaf(l0.y, A0[4*q+1], z0);
                z0 = fmaf(l0.z, A0[4*q+2], z0); z0 = fmaf(l0.w, A0[4*q+3], z0);
                z1 = fmaf(l1.x, A1[4*q+0], z1); z1 = fmaf(l1.y, A1[4*q+1], z1);
                z1 = fmaf(l1.z, A1[4*q+2], z1); z1 = fmaf(l1.w, A1[4*q+3], z1);
                z2 = fmaf(l2.x, A2[4*q+0], z2); z2 = fmaf(l2.y, A2[4*q+1], z2);
                z2 = fmaf(l2.z, A2[4*q+2], z2); z2 = fmaf(l2.w, A2[4*q+3], z2);
                z3 = fmaf(l3.x, A3[4*q+0], z3); z3 = fmaf(l3.y, A3[4*q+1], z3);
                z3 = fmaf(l3.z, A3[4*q+2], z3); z3 = fmaf(l3.w, A3[4*q+3], z3);
            }
            float d;
            d = e0 - z0; acc2 = fmaf(d, d, acc2);
            d = e1 - z1; acc2 = fmaf(d, d, acc2);
            d = e2 - z2; acc2 = fmaf(d, d, acc2);
            d = e3 - z3; acc2 = fmaf(d, d, acc2);
        }
        for (; j < n2; j += s) {
            const float4* __restrict__ L = (const float4*)(latent + (j >> 7) * 20);
            const float* __restrict__ A = sA + (j & 127) * 21;
            float z = 0.f;
            #pragma unroll
            for (int q = 0; q < 5; q++) {
                float4 l = L[q];
                z = fmaf(l.x, A[4*q+0], z); z = fmaf(l.y, A[4*q+1], z);
                z = fmaf(l.z, A[4*q+2], z); z = fmaf(l.w, A[4*q+3], z);
            }
            float d = encoded[j] - z;
            acc2 = fmaf(d, d, acc2);
        }
    }

    // ======== Phase 1: two disjoint paths over disjoint ranges ========
    float acc1 = 0.0f;
    if (is_tma) {
        // ---- TMA ring over tiles [0, nt_tma) ----
        for (int lt = 0; lt < ntiles; lt++) {
            const int slot = lt & (STAGES - 1);
            const unsigned parity = ((unsigned)lt / STAGES) & 1u;
            mbar_wait(mb0 + 8u * slot, parity);

            float4 a = bx[slot][tid];
            float4 c = bd[slot][tid];

            __syncthreads();   // slot drained -> safe to refill
            if (tid == 0 && lt + STAGES < ntiles) {
                const int g = bid + (lt + STAGES) * NB_TMA;
                issue_tile(mb0 + 8u * slot,
                           smem_u32(&bx[slot][0]), smem_u32(&bd[slot][0]),
                           x4 + (size_t)g * TILE_F4, d4 + (size_t)g * TILE_F4);
            }

            float t;
            t = a.x - c.x; acc1 = fmaf(t, t, acc1);
            t = a.y - c.y; acc1 = fmaf(t, t, acc1);
            t = a.z - c.z; acc1 = fmaf(t, t, acc1);
            t = a.w - c.w; acc1 = fmaf(t, t, acc1);
        }
    } else {
        // ---- LDG 4x-unrolled over [nt_tma*TILE_F4, n4) ----
        const int base   = nt_tma * TILE_F4;
        const int lbid   = bid - NB_TMA;
        const int s      = NB_LDG * NTHR;
        int i = base + lbid * NTHR + tid;
        for (; i + 3 * s < n4; i += 4 * s) {
            float4 a0 = x4[i];       float4 c0 = d4[i];
            float4 a1 = x4[i + s];   float4 c1 = d4[i + s];
            float4 a2 = x4[i + 2*s]; float4 c2 = d4[i + 2*s];
            float4 a3 = x4[i + 3*s]; float4 c3 = d4[i + 3*s];
            float t;
            t = a0.x - c0.x; acc1 = fmaf(t, t, acc1);
            t = a0.y - c0.y; acc1 = fmaf(t, t, acc1);
            t = a0.z - c0.z; acc1 = fmaf(t, t, acc1);
            t = a0.w - c0.w; acc1 = fmaf(t, t, acc1);
            t = a1.x - c1.x; acc1 = fmaf(t, t, acc1);
            t = a1.y - c1.y; acc1 = fmaf(t, t, acc1);
            t = a1.z - c1.z; acc1 = fmaf(t, t, acc1);
            t = a1.w - c1.w; acc1 = fmaf(t, t, acc1);
            t = a2.x - c2.x; acc1 = fmaf(t, t, acc1);
            t = a2.y - c2.y; acc1 = fmaf(t, t, acc1);
            t = a2.z - c2.z; acc1 = fmaf(t, t, acc1);
            t = a2.w - c2.w; acc1 = fmaf(t, t, acc1);
            t = a3.x - c3.x; acc1 = fmaf(t, t, acc1);
            t = a3.y - c3.y; acc1 = fmaf(t, t, acc1);
            t = a3.z - c3.z; acc1 = fmaf(t, t, acc1);
            t = a3.w - c3.w; acc1 = fmaf(t, t, acc1);
        }
        for (; i < n4; i += s) {
            float4 a = x4[i], c = d4[i];
            float t;
            t = a.x - c.x; acc1 = fmaf(t, t, acc1);
            t = a.y - c.y; acc1 = fmaf(t, t, acc1);
            t = a.z - c.z; acc1 = fmaf(t, t, acc1);
            t = a.w - c.w; acc1 = fmaf(t, t, acc1);
        }
    }

    // ======== Gram term (block 0): w*Sg with w = 0.1*B/(I*I) ========
    float extra = 0.0f;
    if (bid == 0) {
        float sg = 0.0f;
        for (int t = tid; t < I * I; t += NTHR) {
            const int gi = t / 20, gj = t % 20;
            float acc = 0.0f;
            #pragma unroll 8
            for (int e = 0; e < 128; e++)
                acc = fmaf(sA[e * 21 + gi], sA[e * 21 + gj], acc);
            if (gi == gj) acc -= 1.0f;
            sg = fmaf(acc, acc, sg);
        }
        extra = (0.1f * (float)B / (float)(I * I)) * sg;
    }

    // ======== Deterministic block reduction ========
    red[tid] = acc1 + 1.1f * acc2 + extra;
    __syncthreads();
    for (int s = NTHR / 2; s > 0; s >>= 1) {
        if (tid < s) red[tid] += red[tid + s];
        __syncthreads();
    }

    // ======== Last-block final reduction ========
    __shared__ bool is_last;
    if (tid == 0) {
        g_partials[bid] = red[0];
        __threadfence();
        unsigned int t = atomicAdd(&g_ticket, 1u);
        is_last = (t == (unsigned int)(gridDim.x - 1));
    }
    __syncthreads();

    if (is_last) {
        __threadfence();
        float p = 0.0f;
        for (int k = tid; k < NBLK; k += NTHR)
            p += g_partials[k];
        red[tid] = p;
        __syncthreads();
        for (int s = NTHR / 2; s > 0; s >>= 1) {
            if (tid < s) red[tid] += red[tid + s];
            __syncthreads();
        }
        if (tid == 0) {
            out[0] = red[0] / (float)B;
            g_ticket = 0;
        }
    }
}

extern "C" void kernel_launch(void* const* d_in, const int* in_sizes, int n_in,
                              void* d_out, int out_size)
{
    const float* x       = (const float*)d_in[0];
    const float* encoded = (const float*)d_in[1];
    const float* latent  = (const float*)d_in[2];
    const float* decoded = (const float*)d_in[3];
    const float* rsrA    = (const float*)d_in[4];

    const int I = 20;                  // INTRINSIC
    const int B = in_sizes[2] / I;     // latent [B, I]
    const int E = in_sizes[1] / B;     // encoded [B, E]
    const int D = in_sizes[0] / B;     // x [B, D]

    le_fused<<<NBLK, NTHR>>>(x, decoded, encoded, latent, rsrA,
                             (float*)d_out, B, D, E, I);
}